// round 9
// baseline (speedup 1.0000x reference)
#include <cuda_runtime.h>
#include <cuda_fp16.h>
#include <cstdint>

// ============================================================================
// out[z,k] = sum_{i,j} M[k,i,j] * f1[z,i] * f2[z,j]
// Dense fp16 warp-MMA GEMM (fp32 accum):  out = P @ W
//   P[z, i*32+j] = f1[z,i]*f2[z,j]  (HMUL2 of pre-converted fp16 operands)
//   W[i*32+j, k] = M[k,i,j]         (pre-packed fp16x2 fragment order, RN)
//
// R9 = R8 with a cp.async staged B pipeline:
//   - CTA-cooperative LDGSTS (.cg, L1-bypass) into a 2-slot smem ring,
//     stage = 8 k16-chunks (16KB); always >=1 stage (~500cyc work) in flight
//   - kills the B long-scoreboard stalls AND the 4x per-warp LDG duplication
//   - f1 smem XOR-swizzled (stride 32), f2 pair regs loaded direct from gmem
//     -> exactly 48KB static smem, ~75 regs, 3 CTAs/SM
// ============================================================================

#define N_I 32
#define N_J 32
#define N_K 64
#define Z_CTA 128              // 4 m-groups x 32 rows
#define NTHREADS 256           // 8 warps = 4 m-groups x 2 n-halves
#define N_CHUNKS 64            // K = 1024 / 16
#define N_STAGES 8             // 8 chunks per stage

// Packed W (uint32 = fp16x2), layout unchanged from R7/R8 (validated):
//   uint32 offset = chunk*512 + nhalf*256 + pair*128 + lane*4 + slot
//   slot = nt_local*2 + breg ; n = nhalf*32 + (pair*2+ntl)*8 + qr
//   i = chunk/2 ; j0 = (chunk&1)*16 + 2c + 8*breg ; value = {f16(j0), f16(j0+1)}
__device__ uint32_t g_Wp[N_CHUNKS * 512];   // 128 KB

// ---------------------------------------------------------------------------
__global__ void etp_pack_kernel(const float* __restrict__ Mx) {
    int idx = blockIdx.x * blockDim.x + threadIdx.x;   // 0..32767
    if (idx >= N_CHUNKS * 512) return;
    int chunk = idx >> 9;
    int rem   = idx & 511;
    int nhalf = rem >> 8;
    int r2    = rem & 255;
    int pair  = r2 >> 7;
    int r3    = r2 & 127;
    int lane  = r3 >> 2;
    int slot  = r3 & 3;
    int ntl   = slot >> 1;
    int breg  = slot & 1;
    int qr    = lane >> 2;
    int c     = lane & 3;
    int n     = nhalf * 32 + (pair * 2 + ntl) * 8 + qr;
    int i     = chunk >> 1;
    int j0    = ((chunk & 1) << 4) + 2 * c + 8 * breg;
    float v0 = Mx[n * (N_I * N_J) + i * N_J + j0];
    float v1 = Mx[n * (N_I * N_J) + i * N_J + j0 + 1];
    __half2 h = __floats2half2_rn(v0, v1);             // lo=v0, hi=v1
    g_Wp[idx] = *reinterpret_cast<uint32_t*>(&h);
}

// ---------------------------------------------------------------------------

static __device__ __forceinline__ uint32_t smem_u32(const void* p) {
    uint32_t a;
    asm("{ .reg .u64 t; cvta.to.shared.u64 t, %1; cvt.u32.u64 %0, t; }"
        : "=r"(a) : "l"(p));
    return a;
}

#define CP_ASYNC16(dst_u32, src_ptr) \
    asm volatile("cp.async.cg.shared.global [%0], [%1], 16;" \
                 :: "r"(dst_u32), "l"(src_ptr) : "memory")
#define CP_COMMIT() asm volatile("cp.async.commit_group;" ::: "memory")
#define CP_WAIT1()  asm volatile("cp.async.wait_group 1;" ::: "memory")
#define CP_WAIT0()  asm volatile("cp.async.wait_group 0;" ::: "memory")

#define HMUL2(d, x, y) \
    asm("mul.rn.f16x2 %0, %1, %2;" : "=r"(d) : "r"(x), "r"(y))

#define MMA_F16(cacc, a0, a1, a2, a3, b0, b1)                                 \
    asm volatile(                                                             \
        "mma.sync.aligned.m16n8k16.row.col.f32.f16.f16.f32 "                  \
        "{%0,%1,%2,%3}, {%4,%5,%6,%7}, {%8,%9}, {%0,%1,%2,%3};"               \
        : "+f"((cacc)[0]), "+f"((cacc)[1]), "+f"((cacc)[2]), "+f"((cacc)[3])  \
        : "r"(a0), "r"(a1), "r"(a2), "r"(a3), "r"(b0), "r"(b1))

__global__ void __launch_bounds__(NTHREADS, 3)
etp_mma_kernel(const float* __restrict__ F1,
               const float* __restrict__ F2,
               float* __restrict__ Out) {
    // f1 broadcast half2(v,v), stride 32, XOR-swizzled: word = row*32 + (col ^ ((row&7)<<2))
    __shared__ uint32_t f1h[Z_CTA * 32];                    // 16 KB
    // B ring: 2 slots x 8 chunks x 512 u32
    __shared__ __align__(16) uint32_t ring[2 * 8 * 512];    // 32 KB  (total 48 KB)

    const int tid    = threadIdx.x;
    const int warp   = tid >> 5;
    const int lane   = tid & 31;
    const int mgroup = warp >> 1;        // 0..3, 32 rows each
    const int nhalf  = warp & 1;         // n columns [nhalf*32, +32)
    const int qr     = lane >> 2;        // 0..7
    const int c      = lane & 3;         // 0..3

    const uint32_t ring_base = smem_u32(ring);
    const char* wsrc = reinterpret_cast<const char*>(g_Wp);

    // ---- prologue: stage 0 and 1 in flight (issue before anything else) ----
    {
        const uint32_t d0 = ring_base + tid * 16;
#pragma unroll
        for (int k = 0; k < 4; k++)
            CP_ASYNC16(d0 + k * 4096, wsrc + tid * 16 + k * 4096);
        CP_COMMIT();
        const uint32_t d1 = ring_base + 16384 + tid * 16;
#pragma unroll
        for (int k = 0; k < 4; k++)
            CP_ASYNC16(d1 + k * 4096, wsrc + 16384 + tid * 16 + k * 4096);
        CP_COMMIT();
    }

    // ---- stage f1 (broadcast half2, swizzled) ----
    {
        const float4* f1g = reinterpret_cast<const float4*>(
            F1 + (size_t)blockIdx.x * Z_CTA * N_I);
#pragma unroll
        for (int t = 0; t < 4; t++) {
            int i4 = tid + t * NTHREADS;          // 0..1023
            int row = i4 >> 3, cg = i4 & 7;
            float4 v1 = __ldg(f1g + i4);
            __half2 h0 = __half2half2(__float2half_rn(v1.x));
            __half2 h1 = __half2half2(__float2half_rn(v1.y));
            __half2 h2 = __half2half2(__float2half_rn(v1.z));
            __half2 h3 = __half2half2(__float2half_rn(v1.w));
            uint4 pk;
            pk.x = *reinterpret_cast<uint32_t*>(&h0);
            pk.y = *reinterpret_cast<uint32_t*>(&h1);
            pk.z = *reinterpret_cast<uint32_t*>(&h2);
            pk.w = *reinterpret_cast<uint32_t*>(&h3);
            int col = (cg * 4) ^ ((row & 7) << 2);     // swizzle keeps low 2 bits
            *reinterpret_cast<uint4*>(&f1h[row * 32 + col]) = pk;
        }
    }

    // thread's 4 z rows (local)
    const int r0 = mgroup * 32 + qr;     // rows r0, r0+8, r0+16, r0+24
    const size_t zbase = (size_t)blockIdx.x * Z_CTA;

    // ---- f2 pair regs direct from gmem: s2 = jh*2+breg -> j0 = jh*16+breg*8+2c
    uint32_t f2h[4][4];
#pragma unroll
    for (int rr = 0; rr < 4; rr++) {
        const float* fr = F2 + (zbase + r0 + rr * 8) * N_J;
#pragma unroll
        for (int s2 = 0; s2 < 4; s2++) {
            int jh = s2 >> 1, breg = s2 & 1;
            int j0 = jh * 16 + breg * 8 + 2 * c;
            float2 v = *reinterpret_cast<const float2*>(fr + j0);
            __half2 h = __floats2half2_rn(v.x, v.y);
            f2h[rr][s2] = *reinterpret_cast<uint32_t*>(&h);
        }
    }

    float C[2][4][4];                    // [mtile][ntile][quad]
#pragma unroll
    for (int mt = 0; mt < 2; mt++)
#pragma unroll
        for (int nt = 0; nt < 4; nt++)
#pragma unroll
            for (int q = 0; q < 4; q++) C[mt][nt][q] = 0.0f;

    __syncthreads();                     // f1h visible to all

    const int sw = qr << 2;              // f1 swizzle term (row&7 == qr for all 4 rows)
    const int boff = nhalf * 64 + lane;  // uint4 units within a chunk (128)

#pragma unroll 1
    for (int s = 0; s < N_STAGES; s++) {
        if (s < N_STAGES - 1) { CP_WAIT1(); } else { CP_WAIT0(); }
        __syncthreads();                 // stage s ready for everyone

        const uint4* bs = reinterpret_cast<const uint4*>(ring) + (s & 1) * 1024;

#pragma unroll
        for (int igl = 0; igl < 4; igl++) {
            const int ig = s * 4 + igl;
            uint32_t f1v[4];
#pragma unroll
            for (int rr = 0; rr < 4; rr++)
                f1v[rr] = f1h[(r0 + rr * 8) * 32 + (ig ^ sw)];

#pragma unroll
            for (int jh = 0; jh < 2; jh++) {
                const uint4* bp = bs + (igl * 2 + jh) * 128 + boff;
                const uint4 b0 = bp[0];
                const uint4 b1 = bp[32];

                // A fragments: one HMUL2 each
                uint32_t a[2][4];
#pragma unroll
                for (int mt = 0; mt < 2; mt++) {
                    HMUL2(a[mt][0], f1v[2 * mt],     f2h[2 * mt][jh * 2 + 0]);
                    HMUL2(a[mt][1], f1v[2 * mt + 1], f2h[2 * mt + 1][jh * 2 + 0]);
                    HMUL2(a[mt][2], f1v[2 * mt],     f2h[2 * mt][jh * 2 + 1]);
                    HMUL2(a[mt][3], f1v[2 * mt + 1], f2h[2 * mt + 1][jh * 2 + 1]);
                }

#pragma unroll
                for (int mt = 0; mt < 2; mt++) {
                    MMA_F16(C[mt][0], a[mt][0], a[mt][1], a[mt][2], a[mt][3], b0.x, b0.y);
                    MMA_F16(C[mt][1], a[mt][0], a[mt][1], a[mt][2], a[mt][3], b0.z, b0.w);
                    MMA_F16(C[mt][2], a[mt][0], a[mt][1], a[mt][2], a[mt][3], b1.x, b1.y);
                    MMA_F16(C[mt][3], a[mt][0], a[mt][1], a[mt][2], a[mt][3], b1.z, b1.w);
                }
            }
        }

        __syncthreads();                 // all warps done reading slot s&1
        if (s + 2 < N_STAGES) {          // refill slot with stage s+2
            const uint32_t dst = ring_base + (s & 1) * 16384 + tid * 16;
            const char* src = wsrc + (size_t)(s + 2) * 16384 + tid * 16;
#pragma unroll
            for (int k = 0; k < 4; k++)
                CP_ASYNC16(dst + k * 4096, src + k * 4096);
            CP_COMMIT();
        }
    }

    // ---- epilogue ----
#pragma unroll
    for (int mt = 0; mt < 2; mt++) {
        const size_t z0 = zbase + r0 + mt * 16;
        const size_t z1 = z0 + 8;
#pragma unroll
        for (int nt = 0; nt < 4; nt++) {
            const int col = nhalf * 32 + nt * 8 + 2 * c;
            *reinterpret_cast<float2*>(Out + z0 * N_K + col) =
                make_float2(C[mt][nt][0], C[mt][nt][1]);
            *reinterpret_cast<float2*>(Out + z1 * N_K + col) =
                make_float2(C[mt][nt][2], C[mt][nt][3]);
        }
    }
}

// ---------------------------------------------------------------------------

extern "C" void kernel_launch(void* const* d_in, const int* in_sizes, int n_in,
                              void* d_out, int out_size) {
    const float* f1 = (const float*)d_in[0];   // [Z, 32]
    const float* f2 = (const float*)d_in[1];   // [Z, 32]
    const float* mx = (const float*)d_in[2];   // [64, 32, 32]
    float* out = (float*)d_out;                // [Z, 64]

    const int z_total = in_sizes[0] / N_I;     // 131072
    const int blocks = z_total / Z_CTA;        // 1024

    etp_pack_kernel<<<128, 256>>>(mx);         // 128*256 = 32768
    etp_mma_kernel<<<blocks, NTHREADS>>>(f1, f2, out);
}